// round 9
// baseline (speedup 1.0000x reference)
#include <cuda_runtime.h>

// Fixed problem shapes
#define T_STEPS 5
#define BS      32
#define C       64
#define H       64
#define W       64
#define VTH     1.0f
// gamma = DROP_RATE / BLOCK_SIZE^2 = 0.1 / 49
#define GAMMA   0.002040816326530612f

#define N_PLANES (T_STEPS * BS)               // 160
#define PLANE    (H * W)                      // 4096
#define PLANE4   (PLANE / 4)                  // 1024
#define ELEMS_PER_T (BS * C * H * W)          // 8388608
#define VEC_PER_T   (ELEMS_PER_T / 4)         // 2097152

#define QT_ROWS   16                          // rows per mask block
#define HALO_ROWS (QT_ROWS + 6)               // 22
#define MAX_SEEDS 512                         // E[k] ~ 2.9 per halo tile

// dropblock keep-mask scratch: [160, 64, 64] float (2.62 MB), static device mem
__device__ __align__(16) float d_bm[N_PLANES * PLANE];

// ---------------------------------------------------------------------------
// Kernel 1: sparse-seed block mask. 640 blocks = 160 planes x 4 row-quarters.
// Gather seeds (mr < gamma, ~3 per halo tile) into smem list; each thread
// emits one float4: keep = !(exists seed with Chebyshev dist <= 3).
// ---------------------------------------------------------------------------
__global__ void __launch_bounds__(256) block_mask_kernel(const float4* __restrict__ mr4) {
    __shared__ int s_cnt;
    __shared__ int s_pts[MAX_SEEDS];   // packed (r << 8) | w

    const int n   = blockIdx.x >> 2;          // plane 0..159
    const int q   = blockIdx.x & 3;           // row-quarter 0..3
    const int h0  = q * QT_ROWS;
    const int tid = threadIdx.x;
    if (tid == 0) s_cnt = 0;
    __syncthreads();

    // gather seeds from halo rows [h0-3, h0+18] clamped
    for (int i = tid; i < HALO_ROWS * 16; i += 256) {
        const int r = h0 - 3 + (i >> 4);
        if (r >= 0 && r < H) {
            const int qw = i & 15;
            const float4 v = mr4[n * PLANE4 + r * 16 + qw];
            const int w0 = qw << 2;
            if (v.x < GAMMA) { int s = atomicAdd(&s_cnt, 1); if (s < MAX_SEEDS) s_pts[s] = (r << 8) | (w0 + 0); }
            if (v.y < GAMMA) { int s = atomicAdd(&s_cnt, 1); if (s < MAX_SEEDS) s_pts[s] = (r << 8) | (w0 + 1); }
            if (v.z < GAMMA) { int s = atomicAdd(&s_cnt, 1); if (s < MAX_SEEDS) s_pts[s] = (r << 8) | (w0 + 2); }
            if (v.w < GAMMA) { int s = atomicAdd(&s_cnt, 1); if (s < MAX_SEEDS) s_pts[s] = (r << 8) | (w0 + 3); }
        }
    }
    __syncthreads();

    const int k  = (s_cnt < MAX_SEEDS) ? s_cnt : MAX_SEEDS;
    const int h  = h0 + (tid >> 4);
    const int wq = tid & 15;
    const int wb = wq << 2;

    float4 m = make_float4(1.f, 1.f, 1.f, 1.f);
    for (int i = 0; i < k; ++i) {
        const int p  = s_pts[i];
        const int pr = p >> 8;
        if (abs(pr - h) <= 3) {
            const int dw = (p & 255) - wb;
            if (dw >= -3 && dw <= 3) m.x = 0.f;
            if (dw >= -2 && dw <= 4) m.y = 0.f;
            if (dw >= -1 && dw <= 5) m.z = 0.f;
            if (dw >=  0 && dw <= 6) m.w = 0.f;
        }
    }
    reinterpret_cast<float4*>(d_bm)[n * PLANE4 + h * 16 + wq] = m;

    cudaTriggerProgrammaticLaunchCompletion();
}

// ---------------------------------------------------------------------------
// Kernel 2: LIF scan — R3's lean body (float4 bm loads, FSETP+FSEL select),
// with only xt0/xt1 hoisted before the PDL sync (MLP_p1=2, same as the loop's
// natural depth, so no L1tex front-batch spread penalty).
// ---------------------------------------------------------------------------
__global__ void __launch_bounds__(256) lif_kernel(const float4* __restrict__ x,
                                                  float4* __restrict__ out) {
    const int v = blockIdx.x * 256 + threadIdx.x;   // grid exactly covers VEC_PER_T

    // light prefetch: overlaps the mask kernel via PDL
    const float4 xt0 = x[v];
    const float4 xt1 = x[v + 1 * VEC_PER_T];

    cudaGridDependencySynchronize();

    const int wq = v & 15;
    const int h  = (v >> 4) & 63;
    const int b  = v >> 16;
    const int bm_base = ((b << 6) + h) * 16 + wq;
    const float4* __restrict__ bm4 = reinterpret_cast<const float4*>(d_bm);

    float4 u = make_float4(0.f, 0.f, 0.f, 0.f);

    #define LIF_BODY(XT, BMT, T)                                             \
    {                                                                        \
        float4 o;                                                            \
        u.x = (u.x > VTH) ? XT.x : fmaf(0.5f, u.x, XT.x);                    \
        u.y = (u.y > VTH) ? XT.y : fmaf(0.5f, u.y, XT.y);                    \
        u.z = (u.z > VTH) ? XT.z : fmaf(0.5f, u.z, XT.z);                    \
        u.w = (u.w > VTH) ? XT.w : fmaf(0.5f, u.w, XT.w);                    \
        o.x = (u.x > VTH) ? BMT.x : 0.0f;                                    \
        o.y = (u.y > VTH) ? BMT.y : 0.0f;                                    \
        o.z = (u.z > VTH) ? BMT.z : 0.0f;                                    \
        o.w = (u.w > VTH) ? BMT.w : 0.0f;                                    \
        out[v + T * VEC_PER_T] = o;                                          \
    }

    {
        const float4 bm0 = bm4[(0 * BS) * PLANE4 + bm_base];
        LIF_BODY(xt0, bm0, 0)
    }
    {
        const float4 bm1 = bm4[(1 * BS) * PLANE4 + bm_base];
        LIF_BODY(xt1, bm1, 1)
    }
    #pragma unroll
    for (int t = 2; t < T_STEPS; ++t) {
        const float4 xt  = x[v + t * VEC_PER_T];
        const float4 bmt = bm4[(t * BS) * PLANE4 + bm_base];
        LIF_BODY(xt, bmt, t)
    }
    #undef LIF_BODY
}

extern "C" void kernel_launch(void* const* d_in, const int* in_sizes, int n_in,
                              void* d_out, int out_size) {
    const float4* x  = (const float4*)d_in[0];
    const float4* mr = (const float4*)d_in[1];
    float4* out      = (float4*)d_out;

    block_mask_kernel<<<N_PLANES * 4, 256>>>(mr);

    // PDL launch: lif's 2-deep x-prefetch + launch ramp overlap the mask
    // kernel; the dependency sync gates only the d_bm reads.
    cudaLaunchConfig_t cfg = {};
    cfg.gridDim  = dim3(VEC_PER_T / 256);
    cfg.blockDim = dim3(256);
    cfg.stream   = 0;
    cudaLaunchAttribute attr[1];
    attr[0].id = cudaLaunchAttributeProgrammaticStreamSerialization;
    attr[0].val.programmaticStreamSerializationAllowed = 1;
    cfg.attrs    = attr;
    cfg.numAttrs = 1;
    cudaLaunchKernelEx(&cfg, lif_kernel, x, out);
}